// round 8
// baseline (speedup 1.0000x reference)
#include <cuda_runtime.h>
#include <cuda_bf16.h>
#include <math.h>

#define MAX_N 50000
#define MAX_E 800000
#define CH    96
#define BN_EPS 1e-5f

// -------- scratch (device globals; no allocation allowed) --------
__device__ float d_t   [MAX_N * CH];
__device__ float d_agg [MAX_N * CH];
__device__ float d_stats[4 * CH];
__device__ int   d_deg   [MAX_N];
__device__ int   d_starts[MAX_N + 1];
__device__ int   d_cursor[MAX_N];
__device__ int2  d_epack [MAX_E];

// -------- packed f32x2 helpers --------
__device__ __forceinline__ unsigned long long ffma2(unsigned long long a,
                                                    unsigned long long b,
                                                    unsigned long long c) {
    unsigned long long d;
    asm("fma.rn.f32x2 %0, %1, %2, %3;" : "=l"(d) : "l"(a), "l"(b), "l"(c));
    return d;
}
__device__ __forceinline__ unsigned long long bcast2(float x) {
    unsigned long long d;
    asm("mov.b64 %0, {%1, %1};" : "=l"(d) : "f"(x));
    return d;
}
__device__ __forceinline__ float2 unpack2(unsigned long long p) {
    float lo, hi;
    asm("mov.b64 {%0, %1}, %2;" : "=f"(lo), "=f"(hi) : "l"(p));
    return make_float2(lo, hi);
}

// ============================================================================
// CSR build
// ============================================================================
__global__ void hist_kernel(const int* __restrict__ row, int* __restrict__ deg, int E) {
    int i = blockIdx.x * blockDim.x + threadIdx.x;
    if (i < E) atomicAdd(&deg[row[i]], 1);
}

__global__ void scan_kernel(const int* __restrict__ deg,
                            int* __restrict__ starts,
                            int* __restrict__ cursor,
                            float* __restrict__ stats, int N) {
    __shared__ int part[1024];
    int t = threadIdx.x;
    if (t < 4 * CH) stats[t] = 0.f;
    int chunk = (N + 1023) / 1024;
    int lo = t * chunk;
    int hi = lo + chunk; if (hi > N) hi = N; if (lo > N) lo = N;
    int s = 0;
    for (int i = lo; i < hi; i++) s += deg[i];
    part[t] = s;
    __syncthreads();
    for (int o = 1; o < 1024; o <<= 1) {
        int v = (t >= o) ? part[t - o] : 0;
        __syncthreads();
        part[t] += v;
        __syncthreads();
    }
    int base = (t == 0) ? 0 : part[t - 1];
    for (int i = lo; i < hi; i++) {
        starts[i] = base;
        cursor[i] = base;
        base += deg[i];
    }
    if (t == 1023) starts[N] = part[1023];
}

__global__ void permute_kernel(const int* __restrict__ row,
                               const int* __restrict__ col,
                               const float* __restrict__ ew,
                               int* __restrict__ cursor,
                               int2* __restrict__ epack, int E) {
    int i = blockIdx.x * blockDim.x + threadIdx.x;
    if (i >= E) return;
    int p = atomicAdd(&cursor[row[i]], 1);
    epack[p] = make_int2(col[i], __float_as_int(ew[i]));
}

// ============================================================================
// GEMM: TM=64 rows/block, 8 rows x 4 cols per thread, FFMA2 inner loop.
// K-chunked (KC=32). Optional fused BN+ReLU on input (from raw stats).
// ============================================================================
template<int CIN, int COUT>
__global__ void gemm_bn_kernel(const float* __restrict__ A,
                               const float* __restrict__ W,
                               const float* __restrict__ stats,
                               const float* __restrict__ gamma,
                               const float* __restrict__ beta,
                               float* __restrict__ C, int nrows) {
    constexpr int TM = 64;
    constexpr int KC = 32;
    constexpr int TX = COUT / 4;
    constexpr int TY = 8;
    constexpr int NT = TX * TY;
    constexpr int APAD = TM + 4;   // 68 floats: 16B-aligned rows
    constexpr int KGC = KC / 4;

    __shared__ float Ws[KC * COUT];
    __shared__ float As[KC * APAD];
    __shared__ float Sc[CIN];
    __shared__ float Sh[CIN];

    int tid = threadIdx.y * TX + threadIdx.x;
    int row0 = blockIdx.x * TM;
    int c0 = threadIdx.x * 4;
    int r0 = threadIdx.y * 8;

    bool has_bn = (gamma != nullptr);
    if (has_bn) {
        float n = (float)nrows;
        for (int i = tid; i < CIN; i += NT) {
            float mean = stats[i] / n;
            float var  = stats[CIN + i] / n - mean * mean;
            float inv  = rsqrtf(var + BN_EPS);
            float sc   = gamma[i] * inv;
            Sc[i] = sc;
            Sh[i] = beta[i] - mean * sc;
        }
        __syncthreads();
    }

    // accp[p][c]: packed rows (r0+2p, r0+2p+1), column c0+c
    unsigned long long accp[4][4];
#pragma unroll
    for (int p = 0; p < 4; p++)
#pragma unroll
        for (int c = 0; c < 4; c++) accp[p][c] = 0ULL;

    for (int k0 = 0; k0 < CIN; k0 += KC) {
        for (int i = tid; i < KC * COUT / 4; i += NT)
            ((float4*)Ws)[i] = ((const float4*)(W + k0 * COUT))[i];
        for (int i = tid; i < TM * KGC; i += NT) {
            int r  = i / KGC;
            int kg = i % KGC;
            int grow = row0 + r;
            float4 v = make_float4(0.f, 0.f, 0.f, 0.f);
            if (grow < nrows)
                v = *(const float4*)(A + (long)grow * CIN + k0 + kg * 4);
            if (has_bn) {
                int k = k0 + kg * 4;
                v.x = fmaxf(fmaf(v.x, Sc[k+0], Sh[k+0]), 0.f);
                v.y = fmaxf(fmaf(v.y, Sc[k+1], Sh[k+1]), 0.f);
                v.z = fmaxf(fmaf(v.z, Sc[k+2], Sh[k+2]), 0.f);
                v.w = fmaxf(fmaf(v.w, Sc[k+3], Sh[k+3]), 0.f);
            }
            As[(kg*4+0) * APAD + r] = v.x;
            As[(kg*4+1) * APAD + r] = v.y;
            As[(kg*4+2) * APAD + r] = v.z;
            As[(kg*4+3) * APAD + r] = v.w;
        }
        __syncthreads();

#pragma unroll 4
        for (int kk = 0; kk < KC; kk++) {
            float4 w = *(const float4*)(Ws + kk * COUT + c0);
            ulonglong2 a01 = *(const ulonglong2*)(As + kk * APAD + r0);
            ulonglong2 a23 = *(const ulonglong2*)(As + kk * APAD + r0 + 4);
            unsigned long long wx = bcast2(w.x), wy = bcast2(w.y);
            unsigned long long wz = bcast2(w.z), ww = bcast2(w.w);
            accp[0][0] = ffma2(a01.x, wx, accp[0][0]);
            accp[0][1] = ffma2(a01.x, wy, accp[0][1]);
            accp[0][2] = ffma2(a01.x, wz, accp[0][2]);
            accp[0][3] = ffma2(a01.x, ww, accp[0][3]);
            accp[1][0] = ffma2(a01.y, wx, accp[1][0]);
            accp[1][1] = ffma2(a01.y, wy, accp[1][1]);
            accp[1][2] = ffma2(a01.y, wz, accp[1][2]);
            accp[1][3] = ffma2(a01.y, ww, accp[1][3]);
            accp[2][0] = ffma2(a23.x, wx, accp[2][0]);
            accp[2][1] = ffma2(a23.x, wy, accp[2][1]);
            accp[2][2] = ffma2(a23.x, wz, accp[2][2]);
            accp[2][3] = ffma2(a23.x, ww, accp[2][3]);
            accp[3][0] = ffma2(a23.y, wx, accp[3][0]);
            accp[3][1] = ffma2(a23.y, wy, accp[3][1]);
            accp[3][2] = ffma2(a23.y, wz, accp[3][2]);
            accp[3][3] = ffma2(a23.y, ww, accp[3][3]);
        }
        __syncthreads();
    }

#pragma unroll
    for (int p = 0; p < 4; p++) {
        float2 u0 = unpack2(accp[p][0]);
        float2 u1 = unpack2(accp[p][1]);
        float2 u2 = unpack2(accp[p][2]);
        float2 u3 = unpack2(accp[p][3]);
        int grow = row0 + r0 + p * 2;
        if (grow < nrows)
            *(float4*)(C + (long)grow * COUT + c0) = make_float4(u0.x, u1.x, u2.x, u3.x);
        if (grow + 1 < nrows)
            *(float4*)(C + (long)(grow + 1) * COUT + c0) = make_float4(u0.y, u1.y, u2.y, u3.y);
    }
}

// ============================================================================
// CSR gather (96 ch): one warp per node, lanes 0-23 own float4 groups.
// Two-stage software pipeline: packs prefetched 2 groups ahead, row values
// 1 group ahead; FMA consumes fully-landed data.
// ============================================================================
__global__ void gather96_kernel(const int* __restrict__ starts,
                                const int2* __restrict__ epack,
                                const float* __restrict__ src,
                                float* __restrict__ dst, int N) {
    int w = (blockIdx.x * blockDim.x + threadIdx.x) >> 5;
    int lane = threadIdx.x & 31;
    if (w >= N) return;
    int s = __ldg(starts + w), e = __ldg(starts + w + 1);
    bool act = lane < 24;
    float4 accA = make_float4(0.f,0.f,0.f,0.f);
    float4 accB = make_float4(0.f,0.f,0.f,0.f);
    int i = s;

    if (i + 3 < e) {
        int2 q0 = __ldg(epack + i),     q1 = __ldg(epack + i + 1);
        int2 q2 = __ldg(epack + i + 2), q3 = __ldg(epack + i + 3);
        float4 v0 = make_float4(0,0,0,0), v1 = v0, v2 = v0, v3 = v0;
        if (act) {
            v0 = __ldg(((const float4*)(src + (long)q0.x * 96)) + lane);
            v1 = __ldg(((const float4*)(src + (long)q1.x * 96)) + lane);
            v2 = __ldg(((const float4*)(src + (long)q2.x * 96)) + lane);
            v3 = __ldg(((const float4*)(src + (long)q3.x * 96)) + lane);
        }
        int el = e - 1;
        int2 n0 = __ldg(epack + min(i + 4, el));
        int2 n1 = __ldg(epack + min(i + 5, el));
        int2 n2 = __ldg(epack + min(i + 6, el));
        int2 n3 = __ldg(epack + min(i + 7, el));

        for (; i + 3 < e; ) {
            // prefetch rows for next group (clamped-safe)
            float4 u0 = make_float4(0,0,0,0), u1 = u0, u2 = u0, u3 = u0;
            if (act) {
                u0 = __ldg(((const float4*)(src + (long)n0.x * 96)) + lane);
                u1 = __ldg(((const float4*)(src + (long)n1.x * 96)) + lane);
                u2 = __ldg(((const float4*)(src + (long)n2.x * 96)) + lane);
                u3 = __ldg(((const float4*)(src + (long)n3.x * 96)) + lane);
            }
            // prefetch packs 2 groups ahead
            int2 m0 = __ldg(epack + min(i +  8, el));
            int2 m1 = __ldg(epack + min(i +  9, el));
            int2 m2 = __ldg(epack + min(i + 10, el));
            int2 m3 = __ldg(epack + min(i + 11, el));
            // consume current group (data landed one iteration ago)
            float w0 = __int_as_float(q0.y), w1 = __int_as_float(q1.y);
            float w2 = __int_as_float(q2.y), w3 = __int_as_float(q3.y);
            accA.x = fmaf(w0, v0.x, accA.x); accA.y = fmaf(w0, v0.y, accA.y);
            accA.z = fmaf(w0, v0.z, accA.z); accA.w = fmaf(w0, v0.w, accA.w);
            accB.x = fmaf(w1, v1.x, accB.x); accB.y = fmaf(w1, v1.y, accB.y);
            accB.z = fmaf(w1, v1.z, accB.z); accB.w = fmaf(w1, v1.w, accB.w);
            accA.x = fmaf(w2, v2.x, accA.x); accA.y = fmaf(w2, v2.y, accA.y);
            accA.z = fmaf(w2, v2.z, accA.z); accA.w = fmaf(w2, v2.w, accA.w);
            accB.x = fmaf(w3, v3.x, accB.x); accB.y = fmaf(w3, v3.y, accB.y);
            accB.z = fmaf(w3, v3.z, accB.z); accB.w = fmaf(w3, v3.w, accB.w);
            // rotate
            q0 = n0; q1 = n1; q2 = n2; q3 = n3;
            v0 = u0; v1 = u1; v2 = u2; v3 = u3;
            n0 = m0; n1 = m1; n2 = m2; n3 = m3;
            i += 4;
        }
    }
    // tail (0-3 edges)
    for (; i < e; i++) {
        int2 p = __ldg(epack + i);
        float4 v = make_float4(0,0,0,0);
        if (act) v = __ldg(((const float4*)(src + (long)p.x * 96)) + lane);
        float cw = __int_as_float(p.y);
        accA.x = fmaf(cw, v.x, accA.x); accA.y = fmaf(cw, v.y, accA.y);
        accA.z = fmaf(cw, v.z, accA.z); accA.w = fmaf(cw, v.w, accA.w);
    }
    accA.x += accB.x; accA.y += accB.y; accA.z += accB.z; accA.w += accB.w;
    if (act) ((float4*)(dst + (long)w * 96))[lane] = accA;
}

// ============================================================================
// CSR gather (64 ch): half-warps own alternating edges; pipelined groups of 2
// per half (4 edges in flight). Fused +bias + log_softmax.
// ============================================================================
__global__ void gather64_lsm_kernel(const int* __restrict__ starts,
                                    const int2* __restrict__ epack,
                                    const float* __restrict__ src,
                                    const float* __restrict__ b,
                                    float* __restrict__ out, int N) {
    int w = (blockIdx.x * blockDim.x + threadIdx.x) >> 5;
    int lane = threadIdx.x & 31;
    if (w >= N) return;
    int half = lane >> 4;
    int q = lane & 15;
    int s = __ldg(starts + w), e = __ldg(starts + w + 1);
    float4 accA = make_float4(0.f,0.f,0.f,0.f);
    float4 accB = make_float4(0.f,0.f,0.f,0.f);
    int i = s + half;

    if (i + 2 < e) {
        int el = e - 1;
        int2 q0 = __ldg(epack + i), q1 = __ldg(epack + i + 2);
        float4 v0 = __ldg(((const float4*)(src + (long)q0.x * 64)) + q);
        float4 v1 = __ldg(((const float4*)(src + (long)q1.x * 64)) + q);
        int2 n0 = __ldg(epack + min(i + 4, el));
        int2 n1 = __ldg(epack + min(i + 6, el));
        for (; i + 2 < e; ) {
            float4 u0 = __ldg(((const float4*)(src + (long)n0.x * 64)) + q);
            float4 u1 = __ldg(((const float4*)(src + (long)n1.x * 64)) + q);
            int2 m0 = __ldg(epack + min(i +  8, el));
            int2 m1 = __ldg(epack + min(i + 10, el));
            float w0 = __int_as_float(q0.y), w1 = __int_as_float(q1.y);
            accA.x = fmaf(w0, v0.x, accA.x); accA.y = fmaf(w0, v0.y, accA.y);
            accA.z = fmaf(w0, v0.z, accA.z); accA.w = fmaf(w0, v0.w, accA.w);
            accB.x = fmaf(w1, v1.x, accB.x); accB.y = fmaf(w1, v1.y, accB.y);
            accB.z = fmaf(w1, v1.z, accB.z); accB.w = fmaf(w1, v1.w, accB.w);
            q0 = n0; q1 = n1; v0 = u0; v1 = u1; n0 = m0; n1 = m1;
            i += 4;
        }
    }
    for (; i < e; i += 2) {
        int2 p = __ldg(epack + i);
        float4 v = __ldg(((const float4*)(src + (long)p.x * 64)) + q);
        float cw = __int_as_float(p.y);
        accA.x = fmaf(cw, v.x, accA.x); accA.y = fmaf(cw, v.y, accA.y);
        accA.z = fmaf(cw, v.z, accA.z); accA.w = fmaf(cw, v.w, accA.w);
    }
    accA.x += accB.x; accA.y += accB.y; accA.z += accB.z; accA.w += accB.w;
    accA.x += __shfl_xor_sync(0xFFFFFFFFu, accA.x, 16);
    accA.y += __shfl_xor_sync(0xFFFFFFFFu, accA.y, 16);
    accA.z += __shfl_xor_sync(0xFFFFFFFFu, accA.z, 16);
    accA.w += __shfl_xor_sync(0xFFFFFFFFu, accA.w, 16);
    float4 bb = __ldg(((const float4*)b) + q);
    float v0 = accA.x + bb.x, v1 = accA.y + bb.y, v2 = accA.z + bb.z, v3 = accA.w + bb.w;
    float m = fmaxf(fmaxf(v0, v1), fmaxf(v2, v3));
#pragma unroll
    for (int o = 8; o; o >>= 1) m = fmaxf(m, __shfl_xor_sync(0xFFFFFFFFu, m, o));
    float sm = __expf(v0 - m) + __expf(v1 - m) + __expf(v2 - m) + __expf(v3 - m);
#pragma unroll
    for (int o = 8; o; o >>= 1) sm += __shfl_xor_sync(0xFFFFFFFFu, sm, o);
    float l = m + __logf(sm);
    if (half == 0)
        ((float4*)(out + (long)w * 64))[q] = make_float4(v0 - l, v1 - l, v2 - l, v3 - l);
}

// -------- BN stats: register-accumulating, one thread per channel ----------
__global__ void stats96_kernel(const float* __restrict__ h,
                               float* __restrict__ stats, int nrows) {
    int c = threadIdx.x;
    float s = 0.f, q = 0.f;
    for (int r = blockIdx.x; r < nrows; r += gridDim.x) {
        float v = h[(long)r * 96 + c];
        s += v;
        q = fmaf(v, v, q);
    }
    atomicAdd(&stats[c], s);
    atomicAdd(&stats[96 + c], q);
}

// ============================================================================
extern "C" void kernel_launch(void* const* d_in, const int* in_sizes, int n_in,
                              void* d_out, int out_size) {
    const float* x   = (const float*)d_in[0];
    const float* ew  = (const float*)d_in[1];
    const int*   row = (const int*)  d_in[2];
    const int*   col = (const int*)  d_in[3];
    const float* W1  = (const float*)d_in[4];
    // b1 = d_in[5]  -- absorbed exactly by BatchNorm mean, skipped
    const float* W2  = (const float*)d_in[6];
    // b2 = d_in[7]  -- absorbed exactly by BatchNorm mean, skipped
    const float* W3  = (const float*)d_in[8];
    const float* b3  = (const float*)d_in[9];
    const float* g1  = (const float*)d_in[10];
    const float* be1 = (const float*)d_in[11];
    const float* g2  = (const float*)d_in[12];
    const float* be2 = (const float*)d_in[13];

    int N = in_sizes[0] / 128;
    int E = in_sizes[1];
    if (N > MAX_N) N = MAX_N;
    if (E > MAX_E) E = MAX_E;
    float* out = (float*)d_out;

    float *t, *agg, *stats;
    int *deg, *starts, *cursor;
    int2 *epack;
    cudaGetSymbolAddress((void**)&t,      d_t);
    cudaGetSymbolAddress((void**)&agg,    d_agg);
    cudaGetSymbolAddress((void**)&stats,  d_stats);
    cudaGetSymbolAddress((void**)&deg,    d_deg);
    cudaGetSymbolAddress((void**)&starts, d_starts);
    cudaGetSymbolAddress((void**)&cursor, d_cursor);
    cudaGetSymbolAddress((void**)&epack,  d_epack);

    float* stats1 = stats;
    float* stats2 = stats + 2 * CH;

    int gblocks = (N + 63) / 64;
    int eblocks = (E + 255) / 256;
    int nwarp_blocks = (N * 32 + 255) / 256;

    // ---------------- CSR build (also zeros stats) ----------------
    cudaMemsetAsync(deg, 0, (long)N * sizeof(int));
    hist_kernel<<<eblocks, 256>>>(row, deg, E);
    scan_kernel<<<1, 1024>>>(deg, starts, cursor, stats, N);
    permute_kernel<<<eblocks, 256>>>(row, col, ew, cursor, epack, E);

    // ---------------- Layer 1 ----------------
    gemm_bn_kernel<128,96><<<gblocks, dim3(24,8)>>>(x, W1, nullptr, nullptr, nullptr, t, N);
    gather96_kernel<<<nwarp_blocks, 256>>>(starts, epack, t, agg, N);
    stats96_kernel<<<1024, 96>>>(agg, stats1, N);

    // ---------------- Layer 2 ----------------
    gemm_bn_kernel<96,96><<<gblocks, dim3(24,8)>>>(agg, W2, stats1, g1, be1, t, N);
    gather96_kernel<<<nwarp_blocks, 256>>>(starts, epack, t, agg, N);
    stats96_kernel<<<1024, 96>>>(agg, stats2, N);

    // ---------------- Layer 3 ----------------
    gemm_bn_kernel<96,64><<<gblocks, dim3(16,8)>>>(agg, W3, stats2, g2, be2, t, N);
    gather64_lsm_kernel<<<nwarp_blocks, 256>>>(starts, epack, t, b3, out, N);
}

// round 9
// speedup vs baseline: 1.1183x; 1.1183x over previous
#include <cuda_runtime.h>
#include <cuda_bf16.h>
#include <math.h>

#define MAX_N 50000
#define MAX_E 800000
#define CH    96
#define BN_EPS 1e-5f

// -------- scratch (device globals; no allocation allowed) --------
__device__ float d_t   [MAX_N * CH];
__device__ float d_agg [MAX_N * CH];
__device__ float d_stats[4 * CH];
__device__ int   d_deg   [MAX_N];
__device__ int   d_starts[MAX_N + 1];
__device__ int   d_cursor[MAX_N];
__device__ int2  d_epack [MAX_E];

// -------- packed f32x2 helpers --------
__device__ __forceinline__ unsigned long long ffma2(unsigned long long a,
                                                    unsigned long long b,
                                                    unsigned long long c) {
    unsigned long long d;
    asm("fma.rn.f32x2 %0, %1, %2, %3;" : "=l"(d) : "l"(a), "l"(b), "l"(c));
    return d;
}
__device__ __forceinline__ unsigned long long bcast2(float x) {
    unsigned long long d;
    asm("mov.b64 %0, {%1, %1};" : "=l"(d) : "f"(x));
    return d;
}
__device__ __forceinline__ float2 unpack2(unsigned long long p) {
    float lo, hi;
    asm("mov.b64 {%0, %1}, %2;" : "=f"(lo), "=f"(hi) : "l"(p));
    return make_float2(lo, hi);
}

// ============================================================================
// GEMM device body: TM=32 rows/block, 4x4 per thread, FFMA2 inner loop,
// K-chunked (KC=32). Optional fused BN+ReLU on input (from raw stats).
// ============================================================================
template<int CIN, int COUT>
__device__ __forceinline__ void gemm_bn_body(int bx,
                                             const float* __restrict__ A,
                                             const float* __restrict__ W,
                                             const float* __restrict__ stats,
                                             const float* __restrict__ gamma,
                                             const float* __restrict__ beta,
                                             float* __restrict__ C, int nrows) {
    constexpr int TM = 32;
    constexpr int KC = 32;
    constexpr int TX = COUT / 4;
    constexpr int TY = TM / 4;
    constexpr int NT = TX * TY;
    constexpr int APAD = TM + 4;
    constexpr int KGC = KC / 4;

    __shared__ float Ws[KC * COUT];
    __shared__ float As[KC * APAD];
    __shared__ float Sc[CIN];
    __shared__ float Sh[CIN];

    int tid = threadIdx.y * TX + threadIdx.x;
    int row0 = bx * TM;
    int c0 = threadIdx.x * 4;
    int r0 = threadIdx.y * 4;

    bool has_bn = (gamma != nullptr);
    if (has_bn) {
        float n = (float)nrows;
        for (int i = tid; i < CIN; i += NT) {
            float mean = stats[i] / n;
            float var  = stats[CIN + i] / n - mean * mean;
            float inv  = rsqrtf(var + BN_EPS);
            float sc   = gamma[i] * inv;
            Sc[i] = sc;
            Sh[i] = beta[i] - mean * sc;
        }
        __syncthreads();
    }

    unsigned long long accp[2][4];
#pragma unroll
    for (int rp = 0; rp < 2; rp++)
#pragma unroll
        for (int c = 0; c < 4; c++) accp[rp][c] = 0ULL;

    for (int k0 = 0; k0 < CIN; k0 += KC) {
        for (int i = tid; i < KC * COUT / 4; i += NT)
            ((float4*)Ws)[i] = ((const float4*)(W + k0 * COUT))[i];
        for (int i = tid; i < TM * KGC; i += NT) {
            int r  = i / KGC;
            int kg = i % KGC;
            int grow = row0 + r;
            float4 v = make_float4(0.f, 0.f, 0.f, 0.f);
            if (grow < nrows)
                v = *(const float4*)(A + (long)grow * CIN + k0 + kg * 4);
            if (has_bn) {
                int k = k0 + kg * 4;
                v.x = fmaxf(fmaf(v.x, Sc[k+0], Sh[k+0]), 0.f);
                v.y = fmaxf(fmaf(v.y, Sc[k+1], Sh[k+1]), 0.f);
                v.z = fmaxf(fmaf(v.z, Sc[k+2], Sh[k+2]), 0.f);
                v.w = fmaxf(fmaf(v.w, Sc[k+3], Sh[k+3]), 0.f);
            }
            As[(kg*4+0) * APAD + r] = v.x;
            As[(kg*4+1) * APAD + r] = v.y;
            As[(kg*4+2) * APAD + r] = v.z;
            As[(kg*4+3) * APAD + r] = v.w;
        }
        __syncthreads();

#pragma unroll 8
        for (int kk = 0; kk < KC; kk++) {
            float4 w = *(const float4*)(Ws + kk * COUT + c0);
            ulonglong2 av = *(const ulonglong2*)(As + kk * APAD + r0);
            unsigned long long wx = bcast2(w.x), wy = bcast2(w.y);
            unsigned long long wz = bcast2(w.z), ww = bcast2(w.w);
            accp[0][0] = ffma2(av.x, wx, accp[0][0]);
            accp[0][1] = ffma2(av.x, wy, accp[0][1]);
            accp[0][2] = ffma2(av.x, wz, accp[0][2]);
            accp[0][3] = ffma2(av.x, ww, accp[0][3]);
            accp[1][0] = ffma2(av.y, wx, accp[1][0]);
            accp[1][1] = ffma2(av.y, wy, accp[1][1]);
            accp[1][2] = ffma2(av.y, wz, accp[1][2]);
            accp[1][3] = ffma2(av.y, ww, accp[1][3]);
        }
        __syncthreads();
    }

#pragma unroll
    for (int rp = 0; rp < 2; rp++) {
        float2 u0 = unpack2(accp[rp][0]);
        float2 u1 = unpack2(accp[rp][1]);
        float2 u2 = unpack2(accp[rp][2]);
        float2 u3 = unpack2(accp[rp][3]);
        int grow = row0 + r0 + rp * 2;
        if (grow < nrows)
            *(float4*)(C + (long)grow * COUT + c0) = make_float4(u0.x, u1.x, u2.x, u3.x);
        if (grow + 1 < nrows)
            *(float4*)(C + (long)(grow + 1) * COUT + c0) = make_float4(u0.y, u1.y, u2.y, u3.y);
    }
}

template<int CIN, int COUT>
__global__ void __launch_bounds__(192, 6)
gemm_bn_kernel(const float* __restrict__ A,
               const float* __restrict__ W,
               const float* __restrict__ stats,
               const float* __restrict__ gamma,
               const float* __restrict__ beta,
               float* __restrict__ C, int nrows) {
    gemm_bn_body<CIN, COUT>(blockIdx.x, A, W, stats, gamma, beta, C, nrows);
}

// ---- fused: GEMM1 (blocks [0,gb)) + edge histogram (blocks [gb, gridDim)) ---
__global__ void __launch_bounds__(192, 6)
gemm1_hist_kernel(const float* __restrict__ A,
                  const float* __restrict__ W,
                  float* __restrict__ C, int nrows, int gb,
                  const int* __restrict__ row, int* __restrict__ deg, int E) {
    if (blockIdx.x < gb) {
        gemm_bn_body<128, 96>(blockIdx.x, A, W, nullptr, nullptr, nullptr, C, nrows);
    } else {
        int nb = gridDim.x - gb;
        int i = (blockIdx.x - gb) * blockDim.x * blockDim.y
              + threadIdx.y * blockDim.x + threadIdx.x;
        int stride = nb * blockDim.x * blockDim.y;
        for (; i < E; i += stride) atomicAdd(&deg[row[i]], 1);
    }
}

// ============================================================================
// CSR build: scan (also zeros stats) -> permute
// ============================================================================
__global__ void scan_kernel(const int* __restrict__ deg,
                            int* __restrict__ starts,
                            int* __restrict__ cursor,
                            float* __restrict__ stats, int N) {
    __shared__ int part[1024];
    int t = threadIdx.x;
    if (t < 4 * CH) stats[t] = 0.f;
    int chunk = (N + 1023) / 1024;
    int lo = t * chunk;
    int hi = lo + chunk; if (hi > N) hi = N; if (lo > N) lo = N;
    int s = 0;
    for (int i = lo; i < hi; i++) s += deg[i];
    part[t] = s;
    __syncthreads();
    for (int o = 1; o < 1024; o <<= 1) {
        int v = (t >= o) ? part[t - o] : 0;
        __syncthreads();
        part[t] += v;
        __syncthreads();
    }
    int base = (t == 0) ? 0 : part[t - 1];
    for (int i = lo; i < hi; i++) {
        starts[i] = base;
        cursor[i] = base;
        base += deg[i];
    }
    if (t == 1023) starts[N] = part[1023];
}

__global__ void permute_kernel(const int* __restrict__ row,
                               const int* __restrict__ col,
                               const float* __restrict__ ew,
                               int* __restrict__ cursor,
                               int2* __restrict__ epack, int E) {
    int i = blockIdx.x * blockDim.x + threadIdx.x;
    if (i >= E) return;
    int p = atomicAdd(&cursor[row[i]], 1);
    epack[p] = make_int2(col[i], __float_as_int(ew[i]));
}

// ============================================================================
// CSR gather (96 ch): one warp per node, lanes 0-23 own float4 groups.
// Unrolled by 4 edges (4 LDG.128 in flight).
// ============================================================================
__global__ void gather96_kernel(const int* __restrict__ starts,
                                const int2* __restrict__ epack,
                                const float* __restrict__ src,
                                float* __restrict__ dst, int N) {
    int w = (blockIdx.x * blockDim.x + threadIdx.x) >> 5;
    int lane = threadIdx.x & 31;
    if (w >= N) return;
    int s = __ldg(starts + w), e = __ldg(starts + w + 1);
    bool act = lane < 24;
    float4 acc0 = make_float4(0.f,0.f,0.f,0.f);
    float4 acc1 = make_float4(0.f,0.f,0.f,0.f);
    int i = s;
    for (; i + 3 < e; i += 4) {
        int2 p0 = __ldg(epack + i);
        int2 p1 = __ldg(epack + i + 1);
        int2 p2 = __ldg(epack + i + 2);
        int2 p3 = __ldg(epack + i + 3);
        float4 v0 = make_float4(0,0,0,0), v1 = v0, v2 = v0, v3 = v0;
        if (act) {
            v0 = __ldg(((const float4*)(src + (long)p0.x * 96)) + lane);
            v1 = __ldg(((const float4*)(src + (long)p1.x * 96)) + lane);
            v2 = __ldg(((const float4*)(src + (long)p2.x * 96)) + lane);
            v3 = __ldg(((const float4*)(src + (long)p3.x * 96)) + lane);
        }
        float w0 = __int_as_float(p0.y), w1 = __int_as_float(p1.y);
        float w2 = __int_as_float(p2.y), w3 = __int_as_float(p3.y);
        acc0.x = fmaf(w0, v0.x, acc0.x); acc0.y = fmaf(w0, v0.y, acc0.y);
        acc0.z = fmaf(w0, v0.z, acc0.z); acc0.w = fmaf(w0, v0.w, acc0.w);
        acc1.x = fmaf(w1, v1.x, acc1.x); acc1.y = fmaf(w1, v1.y, acc1.y);
        acc1.z = fmaf(w1, v1.z, acc1.z); acc1.w = fmaf(w1, v1.w, acc1.w);
        acc0.x = fmaf(w2, v2.x, acc0.x); acc0.y = fmaf(w2, v2.y, acc0.y);
        acc0.z = fmaf(w2, v2.z, acc0.z); acc0.w = fmaf(w2, v2.w, acc0.w);
        acc1.x = fmaf(w3, v3.x, acc1.x); acc1.y = fmaf(w3, v3.y, acc1.y);
        acc1.z = fmaf(w3, v3.z, acc1.z); acc1.w = fmaf(w3, v3.w, acc1.w);
    }
    for (; i < e; i++) {
        int2 p = __ldg(epack + i);
        float4 v = make_float4(0,0,0,0);
        if (act) v = __ldg(((const float4*)(src + (long)p.x * 96)) + lane);
        float cw = __int_as_float(p.y);
        acc0.x = fmaf(cw, v.x, acc0.x); acc0.y = fmaf(cw, v.y, acc0.y);
        acc0.z = fmaf(cw, v.z, acc0.z); acc0.w = fmaf(cw, v.w, acc0.w);
    }
    acc0.x += acc1.x; acc0.y += acc1.y; acc0.z += acc1.z; acc0.w += acc1.w;
    if (act) ((float4*)(dst + (long)w * 96))[lane] = acc0;
}

// ============================================================================
// CSR gather (64 ch): half-warps own alternating edges, unroll-2 per half.
// Fused +bias + log_softmax.
// ============================================================================
__global__ void gather64_lsm_kernel(const int* __restrict__ starts,
                                    const int2* __restrict__ epack,
                                    const float* __restrict__ src,
                                    const float* __restrict__ b,
                                    float* __restrict__ out, int N) {
    int w = (blockIdx.x * blockDim.x + threadIdx.x) >> 5;
    int lane = threadIdx.x & 31;
    if (w >= N) return;
    int half = lane >> 4;
    int q = lane & 15;
    int s = __ldg(starts + w), e = __ldg(starts + w + 1);
    float4 acc0 = make_float4(0.f,0.f,0.f,0.f);
    float4 acc1 = make_float4(0.f,0.f,0.f,0.f);
    int i = s + half;
    for (; i + 2 < e; i += 4) {
        int2 p0 = __ldg(epack + i);
        int2 p1 = __ldg(epack + i + 2);
        float4 v0 = __ldg(((const float4*)(src + (long)p0.x * 64)) + q);
        float4 v1 = __ldg(((const float4*)(src + (long)p1.x * 64)) + q);
        float w0 = __int_as_float(p0.y), w1 = __int_as_float(p1.y);
        acc0.x = fmaf(w0, v0.x, acc0.x); acc0.y = fmaf(w0, v0.y, acc0.y);
        acc0.z = fmaf(w0, v0.z, acc0.z); acc0.w = fmaf(w0, v0.w, acc0.w);
        acc1.x = fmaf(w1, v1.x, acc1.x); acc1.y = fmaf(w1, v1.y, acc1.y);
        acc1.z = fmaf(w1, v1.z, acc1.z); acc1.w = fmaf(w1, v1.w, acc1.w);
    }
    for (; i < e; i += 2) {
        int2 p = __ldg(epack + i);
        float4 v = __ldg(((const float4*)(src + (long)p.x * 64)) + q);
        float cw = __int_as_float(p.y);
        acc0.x = fmaf(cw, v.x, acc0.x); acc0.y = fmaf(cw, v.y, acc0.y);
        acc0.z = fmaf(cw, v.z, acc0.z); acc0.w = fmaf(cw, v.w, acc0.w);
    }
    acc0.x += acc1.x; acc0.y += acc1.y; acc0.z += acc1.z; acc0.w += acc1.w;
    acc0.x += __shfl_xor_sync(0xFFFFFFFFu, acc0.x, 16);
    acc0.y += __shfl_xor_sync(0xFFFFFFFFu, acc0.y, 16);
    acc0.z += __shfl_xor_sync(0xFFFFFFFFu, acc0.z, 16);
    acc0.w += __shfl_xor_sync(0xFFFFFFFFu, acc0.w, 16);
    float4 bb = __ldg(((const float4*)b) + q);
    float v0 = acc0.x + bb.x, v1 = acc0.y + bb.y, v2 = acc0.z + bb.z, v3 = acc0.w + bb.w;
    float m = fmaxf(fmaxf(v0, v1), fmaxf(v2, v3));
#pragma unroll
    for (int o = 8; o; o >>= 1) m = fmaxf(m, __shfl_xor_sync(0xFFFFFFFFu, m, o));
    float sm = __expf(v0 - m) + __expf(v1 - m) + __expf(v2 - m) + __expf(v3 - m);
#pragma unroll
    for (int o = 8; o; o >>= 1) sm += __shfl_xor_sync(0xFFFFFFFFu, sm, o);
    float l = m + __logf(sm);
    if (half == 0)
        ((float4*)(out + (long)w * 64))[q] = make_float4(v0 - l, v1 - l, v2 - l, v3 - l);
}

// -------- BN stats: register-accumulating, one thread per channel ----------
__global__ void stats96_kernel(const float* __restrict__ h,
                               float* __restrict__ stats, int nrows) {
    int c = threadIdx.x;
    float s = 0.f, q = 0.f;
    for (int r = blockIdx.x; r < nrows; r += gridDim.x) {
        float v = h[(long)r * 96 + c];
        s += v;
        q = fmaf(v, v, q);
    }
    atomicAdd(&stats[c], s);
    atomicAdd(&stats[96 + c], q);
}

// ============================================================================
extern "C" void kernel_launch(void* const* d_in, const int* in_sizes, int n_in,
                              void* d_out, int out_size) {
    const float* x   = (const float*)d_in[0];
    const float* ew  = (const float*)d_in[1];
    const int*   row = (const int*)  d_in[2];
    const int*   col = (const int*)  d_in[3];
    const float* W1  = (const float*)d_in[4];
    // b1 = d_in[5]  -- absorbed exactly by BatchNorm mean, skipped
    const float* W2  = (const float*)d_in[6];
    // b2 = d_in[7]  -- absorbed exactly by BatchNorm mean, skipped
    const float* W3  = (const float*)d_in[8];
    const float* b3  = (const float*)d_in[9];
    const float* g1  = (const float*)d_in[10];
    const float* be1 = (const float*)d_in[11];
    const float* g2  = (const float*)d_in[12];
    const float* be2 = (const float*)d_in[13];

    int N = in_sizes[0] / 128;
    int E = in_sizes[1];
    if (N > MAX_N) N = MAX_N;
    if (E > MAX_E) E = MAX_E;
    float* out = (float*)d_out;

    float *t, *agg, *stats;
    int *deg, *starts, *cursor;
    int2 *epack;
    cudaGetSymbolAddress((void**)&t,      d_t);
    cudaGetSymbolAddress((void**)&agg,    d_agg);
    cudaGetSymbolAddress((void**)&stats,  d_stats);
    cudaGetSymbolAddress((void**)&deg,    d_deg);
    cudaGetSymbolAddress((void**)&starts, d_starts);
    cudaGetSymbolAddress((void**)&cursor, d_cursor);
    cudaGetSymbolAddress((void**)&epack,  d_epack);

    float* stats1 = stats;
    float* stats2 = stats + 2 * CH;

    int gblocks = (N + 31) / 32;
    int eblocks = (E + 255) / 256;
    int nwarp_blocks = (N * 32 + 255) / 256;
    int hblocks = 512;   // histogram blocks appended to GEMM1's grid

    // ---------------- fused GEMM1 + histogram, then scan + permute ----------
    cudaMemsetAsync(deg, 0, (long)N * sizeof(int));
    gemm1_hist_kernel<<<gblocks + hblocks, dim3(24,8)>>>(x, W1, t, N, gblocks,
                                                         row, deg, E);
    scan_kernel<<<1, 1024>>>(deg, starts, cursor, stats, N);
    permute_kernel<<<eblocks, 256>>>(row, col, ew, cursor, epack, E);

    // ---------------- Layer 1 (aggregate + stats) ----------------
    gather96_kernel<<<nwarp_blocks, 256>>>(starts, epack, t, agg, N);
    stats96_kernel<<<1024, 96>>>(agg, stats1, N);

    // ---------------- Layer 2 ----------------
    gemm_bn_kernel<96,96><<<gblocks, dim3(24,8)>>>(agg, W2, stats1, g1, be1, t, N);
    gather96_kernel<<<nwarp_blocks, 256>>>(starts, epack, t, agg, N);
    stats96_kernel<<<1024, 96>>>(agg, stats2, N);

    // ---------------- Layer 3 ----------------
    gemm_bn_kernel<96,64><<<gblocks, dim3(16,8)>>>(agg, W3, stats2, g2, be2, t, N);
    gather64_lsm_kernel<<<nwarp_blocks, 256>>>(starts, epack, t, b3, out, N);
}

// round 10
// speedup vs baseline: 1.1557x; 1.0335x over previous
#include <cuda_runtime.h>
#include <cuda_fp16.h>
#include <math.h>

#define MAX_N 50000
#define MAX_E 800000
#define CH    96
#define BN_EPS 1e-5f

// -------- scratch (device globals; no allocation allowed) --------
__device__ __half d_t [MAX_N * CH];      // GEMM output (fp16, gather input)
__device__ float  d_agg[MAX_N * CH];     // aggregation output (fp32)
__device__ float  d_stats[4 * CH];
__device__ int    d_deg   [MAX_N];
__device__ int    d_starts[MAX_N + 1];
__device__ int    d_cursor[MAX_N];
__device__ int2   d_epack [MAX_E];

// -------- packed f32x2 helpers --------
__device__ __forceinline__ unsigned long long ffma2(unsigned long long a,
                                                    unsigned long long b,
                                                    unsigned long long c) {
    unsigned long long d;
    asm("fma.rn.f32x2 %0, %1, %2, %3;" : "=l"(d) : "l"(a), "l"(b), "l"(c));
    return d;
}
__device__ __forceinline__ unsigned long long bcast2(float x) {
    unsigned long long d;
    asm("mov.b64 %0, {%1, %1};" : "=l"(d) : "f"(x));
    return d;
}
__device__ __forceinline__ float2 unpack2(unsigned long long p) {
    float lo, hi;
    asm("mov.b64 {%0, %1}, %2;" : "=f"(lo), "=f"(hi) : "l"(p));
    return make_float2(lo, hi);
}

// ============================================================================
// GEMM device body: TM=32 rows/block, 4x4 per thread, FFMA2 inner loop,
// K-chunked (KC=32). Optional fused BN+ReLU on input. fp16 output.
// ============================================================================
template<int CIN, int COUT>
__device__ __forceinline__ void gemm_bn_body(int bx,
                                             const float* __restrict__ A,
                                             const float* __restrict__ W,
                                             const float* __restrict__ stats,
                                             const float* __restrict__ gamma,
                                             const float* __restrict__ beta,
                                             __half* __restrict__ C, int nrows) {
    constexpr int TM = 32;
    constexpr int KC = 32;
    constexpr int TX = COUT / 4;
    constexpr int TY = TM / 4;
    constexpr int NT = TX * TY;
    constexpr int APAD = TM + 4;
    constexpr int KGC = KC / 4;

    __shared__ float Ws[KC * COUT];
    __shared__ float As[KC * APAD];
    __shared__ float Sc[CIN];
    __shared__ float Sh[CIN];

    int tid = threadIdx.y * TX + threadIdx.x;
    int row0 = bx * TM;
    int c0 = threadIdx.x * 4;
    int r0 = threadIdx.y * 4;

    bool has_bn = (gamma != nullptr);
    if (has_bn) {
        float n = (float)nrows;
        for (int i = tid; i < CIN; i += NT) {
            float mean = stats[i] / n;
            float var  = stats[CIN + i] / n - mean * mean;
            float inv  = rsqrtf(var + BN_EPS);
            float sc   = gamma[i] * inv;
            Sc[i] = sc;
            Sh[i] = beta[i] - mean * sc;
        }
        __syncthreads();
    }

    unsigned long long accp[2][4];
#pragma unroll
    for (int rp = 0; rp < 2; rp++)
#pragma unroll
        for (int c = 0; c < 4; c++) accp[rp][c] = 0ULL;

    for (int k0 = 0; k0 < CIN; k0 += KC) {
        for (int i = tid; i < KC * COUT / 4; i += NT)
            ((float4*)Ws)[i] = ((const float4*)(W + k0 * COUT))[i];
        for (int i = tid; i < TM * KGC; i += NT) {
            int r  = i / KGC;
            int kg = i % KGC;
            int grow = row0 + r;
            float4 v = make_float4(0.f, 0.f, 0.f, 0.f);
            if (grow < nrows)
                v = *(const float4*)(A + (long)grow * CIN + k0 + kg * 4);
            if (has_bn) {
                int k = k0 + kg * 4;
                v.x = fmaxf(fmaf(v.x, Sc[k+0], Sh[k+0]), 0.f);
                v.y = fmaxf(fmaf(v.y, Sc[k+1], Sh[k+1]), 0.f);
                v.z = fmaxf(fmaf(v.z, Sc[k+2], Sh[k+2]), 0.f);
                v.w = fmaxf(fmaf(v.w, Sc[k+3], Sh[k+3]), 0.f);
            }
            As[(kg*4+0) * APAD + r] = v.x;
            As[(kg*4+1) * APAD + r] = v.y;
            As[(kg*4+2) * APAD + r] = v.z;
            As[(kg*4+3) * APAD + r] = v.w;
        }
        __syncthreads();

#pragma unroll 8
        for (int kk = 0; kk < KC; kk++) {
            float4 w = *(const float4*)(Ws + kk * COUT + c0);
            ulonglong2 av = *(const ulonglong2*)(As + kk * APAD + r0);
            unsigned long long wx = bcast2(w.x), wy = bcast2(w.y);
            unsigned long long wz = bcast2(w.z), ww = bcast2(w.w);
            accp[0][0] = ffma2(av.x, wx, accp[0][0]);
            accp[0][1] = ffma2(av.x, wy, accp[0][1]);
            accp[0][2] = ffma2(av.x, wz, accp[0][2]);
            accp[0][3] = ffma2(av.x, ww, accp[0][3]);
            accp[1][0] = ffma2(av.y, wx, accp[1][0]);
            accp[1][1] = ffma2(av.y, wy, accp[1][1]);
            accp[1][2] = ffma2(av.y, wz, accp[1][2]);
            accp[1][3] = ffma2(av.y, ww, accp[1][3]);
        }
        __syncthreads();
    }

#pragma unroll
    for (int rp = 0; rp < 2; rp++) {
        float2 u0 = unpack2(accp[rp][0]);
        float2 u1 = unpack2(accp[rp][1]);
        float2 u2 = unpack2(accp[rp][2]);
        float2 u3 = unpack2(accp[rp][3]);
        int grow = row0 + r0 + rp * 2;
        if (grow < nrows) {
            __half2 h01 = __floats2half2_rn(u0.x, u1.x);
            __half2 h23 = __floats2half2_rn(u2.x, u3.x);
            uint2 pkt = make_uint2(*(unsigned*)&h01, *(unsigned*)&h23);
            *(uint2*)(C + (long)grow * COUT + c0) = pkt;
        }
        if (grow + 1 < nrows) {
            __half2 h01 = __floats2half2_rn(u0.y, u1.y);
            __half2 h23 = __floats2half2_rn(u2.y, u3.y);
            uint2 pkt = make_uint2(*(unsigned*)&h01, *(unsigned*)&h23);
            *(uint2*)(C + (long)(grow + 1) * COUT + c0) = pkt;
        }
    }
}

template<int CIN, int COUT>
__global__ void __launch_bounds__(192, 6)
gemm_bn_kernel(const float* __restrict__ A,
               const float* __restrict__ W,
               const float* __restrict__ stats,
               const float* __restrict__ gamma,
               const float* __restrict__ beta,
               __half* __restrict__ C, int nrows) {
    gemm_bn_body<CIN, COUT>(blockIdx.x, A, W, stats, gamma, beta, C, nrows);
}

// ---- fused: GEMM1 (blocks [0,gb)) + edge histogram (blocks [gb, gridDim)) ---
__global__ void __launch_bounds__(192, 6)
gemm1_hist_kernel(const float* __restrict__ A,
                  const float* __restrict__ W,
                  __half* __restrict__ C, int nrows, int gb,
                  const int* __restrict__ row, int* __restrict__ deg, int E) {
    if (blockIdx.x < gb) {
        gemm_bn_body<128, 96>(blockIdx.x, A, W, nullptr, nullptr, nullptr, C, nrows);
    } else {
        int nb = gridDim.x - gb;
        int i = (blockIdx.x - gb) * blockDim.x * blockDim.y
              + threadIdx.y * blockDim.x + threadIdx.x;
        int stride = nb * blockDim.x * blockDim.y;
        for (; i < E; i += stride) atomicAdd(&deg[row[i]], 1);
    }
}

// ============================================================================
// CSR build: scan (also zeros stats) -> permute
// ============================================================================
__global__ void scan_kernel(const int* __restrict__ deg,
                            int* __restrict__ starts,
                            int* __restrict__ cursor,
                            float* __restrict__ stats, int N) {
    __shared__ int part[1024];
    int t = threadIdx.x;
    if (t < 4 * CH) stats[t] = 0.f;
    int chunk = (N + 1023) / 1024;
    int lo = t * chunk;
    int hi = lo + chunk; if (hi > N) hi = N; if (lo > N) lo = N;
    int s = 0;
    for (int i = lo; i < hi; i++) s += deg[i];
    part[t] = s;
    __syncthreads();
    for (int o = 1; o < 1024; o <<= 1) {
        int v = (t >= o) ? part[t - o] : 0;
        __syncthreads();
        part[t] += v;
        __syncthreads();
    }
    int base = (t == 0) ? 0 : part[t - 1];
    for (int i = lo; i < hi; i++) {
        starts[i] = base;
        cursor[i] = base;
        base += deg[i];
    }
    if (t == 1023) starts[N] = part[1023];
}

__global__ void permute_kernel(const int* __restrict__ row,
                               const int* __restrict__ col,
                               const float* __restrict__ ew,
                               int* __restrict__ cursor,
                               int2* __restrict__ epack, int E) {
    int i = blockIdx.x * blockDim.x + threadIdx.x;
    if (i >= E) return;
    int p = atomicAdd(&cursor[row[i]], 1);
    epack[p] = make_int2(col[i], __float_as_int(ew[i]));
}

// ============================================================================
// CSR gather (96 ch, fp16 src): one warp per node, lanes 0-23 own 4-channel
// groups (uint2 = 4 halves = 8B). Unrolled by 4 edges. fp32 accumulate.
// ============================================================================
__device__ __forceinline__ void h4fma(float4& acc, uint2 r, float w) {
    float2 f01 = __half22float2(*(__half2*)&r.x);
    float2 f23 = __half22float2(*(__half2*)&r.y);
    acc.x = fmaf(w, f01.x, acc.x);
    acc.y = fmaf(w, f01.y, acc.y);
    acc.z = fmaf(w, f23.x, acc.z);
    acc.w = fmaf(w, f23.y, acc.w);
}

__global__ void gather96_kernel(const int* __restrict__ starts,
                                const int2* __restrict__ epack,
                                const __half* __restrict__ src,
                                float* __restrict__ dst, int N) {
    int w = (blockIdx.x * blockDim.x + threadIdx.x) >> 5;
    int lane = threadIdx.x & 31;
    if (w >= N) return;
    int s = __ldg(starts + w), e = __ldg(starts + w + 1);
    bool act = lane < 24;
    float4 acc0 = make_float4(0.f,0.f,0.f,0.f);
    float4 acc1 = make_float4(0.f,0.f,0.f,0.f);
    int i = s;
    for (; i + 3 < e; i += 4) {
        int2 p0 = __ldg(epack + i);
        int2 p1 = __ldg(epack + i + 1);
        int2 p2 = __ldg(epack + i + 2);
        int2 p3 = __ldg(epack + i + 3);
        uint2 v0 = make_uint2(0,0), v1 = v0, v2 = v0, v3 = v0;
        if (act) {
            v0 = __ldg(((const uint2*)(src + (long)p0.x * 96)) + lane);
            v1 = __ldg(((const uint2*)(src + (long)p1.x * 96)) + lane);
            v2 = __ldg(((const uint2*)(src + (long)p2.x * 96)) + lane);
            v3 = __ldg(((const uint2*)(src + (long)p3.x * 96)) + lane);
        }
        h4fma(acc0, v0, __int_as_float(p0.y));
        h4fma(acc1, v1, __int_as_float(p1.y));
        h4fma(acc0, v2, __int_as_float(p2.y));
        h4fma(acc1, v3, __int_as_float(p3.y));
    }
    for (; i < e; i++) {
        int2 p = __ldg(epack + i);
        uint2 v = make_uint2(0,0);
        if (act) v = __ldg(((const uint2*)(src + (long)p.x * 96)) + lane);
        h4fma(acc0, v, __int_as_float(p.y));
    }
    acc0.x += acc1.x; acc0.y += acc1.y; acc0.z += acc1.z; acc0.w += acc1.w;
    if (act) ((float4*)(dst + (long)w * 96))[lane] = acc0;
}

// ============================================================================
// CSR gather (64 ch, fp16 src): half-warps own alternating edges, unroll-2
// per half. Fused +bias + log_softmax.
// ============================================================================
__global__ void gather64_lsm_kernel(const int* __restrict__ starts,
                                    const int2* __restrict__ epack,
                                    const __half* __restrict__ src,
                                    const float* __restrict__ b,
                                    float* __restrict__ out, int N) {
    int w = (blockIdx.x * blockDim.x + threadIdx.x) >> 5;
    int lane = threadIdx.x & 31;
    if (w >= N) return;
    int half_ = lane >> 4;
    int q = lane & 15;
    int s = __ldg(starts + w), e = __ldg(starts + w + 1);
    float4 acc0 = make_float4(0.f,0.f,0.f,0.f);
    float4 acc1 = make_float4(0.f,0.f,0.f,0.f);
    int i = s + half_;
    for (; i + 2 < e; i += 4) {
        int2 p0 = __ldg(epack + i);
        int2 p1 = __ldg(epack + i + 2);
        uint2 v0 = __ldg(((const uint2*)(src + (long)p0.x * 64)) + q);
        uint2 v1 = __ldg(((const uint2*)(src + (long)p1.x * 64)) + q);
        h4fma(acc0, v0, __int_as_float(p0.y));
        h4fma(acc1, v1, __int_as_float(p1.y));
    }
    for (; i < e; i += 2) {
        int2 p = __ldg(epack + i);
        uint2 v = __ldg(((const uint2*)(src + (long)p.x * 64)) + q);
        h4fma(acc0, v, __int_as_float(p.y));
    }
    acc0.x += acc1.x; acc0.y += acc1.y; acc0.z += acc1.z; acc0.w += acc1.w;
    acc0.x += __shfl_xor_sync(0xFFFFFFFFu, acc0.x, 16);
    acc0.y += __shfl_xor_sync(0xFFFFFFFFu, acc0.y, 16);
    acc0.z += __shfl_xor_sync(0xFFFFFFFFu, acc0.z, 16);
    acc0.w += __shfl_xor_sync(0xFFFFFFFFu, acc0.w, 16);
    float4 bb = __ldg(((const float4*)b) + q);
    float v0 = acc0.x + bb.x, v1 = acc0.y + bb.y, v2 = acc0.z + bb.z, v3 = acc0.w + bb.w;
    float m = fmaxf(fmaxf(v0, v1), fmaxf(v2, v3));
#pragma unroll
    for (int o = 8; o; o >>= 1) m = fmaxf(m, __shfl_xor_sync(0xFFFFFFFFu, m, o));
    float sm = __expf(v0 - m) + __expf(v1 - m) + __expf(v2 - m) + __expf(v3 - m);
#pragma unroll
    for (int o = 8; o; o >>= 1) sm += __shfl_xor_sync(0xFFFFFFFFu, sm, o);
    float l = m + __logf(sm);
    if (half_ == 0)
        ((float4*)(out + (long)w * 64))[q] = make_float4(v0 - l, v1 - l, v2 - l, v3 - l);
}

// -------- BN stats: register-accumulating, one thread per channel ----------
__global__ void stats96_kernel(const float* __restrict__ h,
                               float* __restrict__ stats, int nrows) {
    int c = threadIdx.x;
    float s = 0.f, q = 0.f;
    for (int r = blockIdx.x; r < nrows; r += gridDim.x) {
        float v = h[(long)r * 96 + c];
        s += v;
        q = fmaf(v, v, q);
    }
    atomicAdd(&stats[c], s);
    atomicAdd(&stats[96 + c], q);
}

// ============================================================================
extern "C" void kernel_launch(void* const* d_in, const int* in_sizes, int n_in,
                              void* d_out, int out_size) {
    const float* x   = (const float*)d_in[0];
    const float* ew  = (const float*)d_in[1];
    const int*   row = (const int*)  d_in[2];
    const int*   col = (const int*)  d_in[3];
    const float* W1  = (const float*)d_in[4];
    // b1 = d_in[5]  -- absorbed exactly by BatchNorm mean, skipped
    const float* W2  = (const float*)d_in[6];
    // b2 = d_in[7]  -- absorbed exactly by BatchNorm mean, skipped
    const float* W3  = (const float*)d_in[8];
    const float* b3  = (const float*)d_in[9];
    const float* g1  = (const float*)d_in[10];
    const float* be1 = (const float*)d_in[11];
    const float* g2  = (const float*)d_in[12];
    const float* be2 = (const float*)d_in[13];

    int N = in_sizes[0] / 128;
    int E = in_sizes[1];
    if (N > MAX_N) N = MAX_N;
    if (E > MAX_E) E = MAX_E;
    float* out = (float*)d_out;

    __half* t;
    float *agg, *stats;
    int *deg, *starts, *cursor;
    int2 *epack;
    cudaGetSymbolAddress((void**)&t,      d_t);
    cudaGetSymbolAddress((void**)&agg,    d_agg);
    cudaGetSymbolAddress((void**)&stats,  d_stats);
    cudaGetSymbolAddress((void**)&deg,    d_deg);
    cudaGetSymbolAddress((void**)&starts, d_starts);
    cudaGetSymbolAddress((void**)&cursor, d_cursor);
    cudaGetSymbolAddress((void**)&epack,  d_epack);

    float* stats1 = stats;
    float* stats2 = stats + 2 * CH;

    int gblocks = (N + 31) / 32;
    int eblocks = (E + 255) / 256;
    int nwarp_blocks = (N * 32 + 255) / 256;
    int hblocks = 512;

    // ---------------- fused GEMM1 + histogram, then scan + permute ----------
    cudaMemsetAsync(deg, 0, (long)N * sizeof(int));
    gemm1_hist_kernel<<<gblocks + hblocks, dim3(24,8)>>>(x, W1, t, N, gblocks,
                                                         row, deg, E);
    scan_kernel<<<1, 1024>>>(deg, starts, cursor, stats, N);
    permute_kernel<<<eblocks, 256>>>(row, col, ew, cursor, epack, E);

    // ---------------- Layer 1 (aggregate + stats) ----------------
    gather96_kernel<<<nwarp_blocks, 256>>>(starts, epack, t, agg, N);
    stats96_kernel<<<1024, 96>>>(agg, stats1, N);

    // ---------------- Layer 2 ----------------
    gemm_bn_kernel<96,96><<<gblocks, dim3(24,8)>>>(agg, W2, stats1, g1, be1, t, N);
    gather96_kernel<<<nwarp_blocks, 256>>>(starts, epack, t, agg, N);
    stats96_kernel<<<1024, 96>>>(agg, stats2, N);

    // ---------------- Layer 3 ----------------
    gemm_bn_kernel<96,64><<<gblocks, dim3(16,8)>>>(agg, W3, stats2, g2, be2, t, N);
    gather64_lsm_kernel<<<nwarp_blocks, 256>>>(starts, epack, t, b3, out, N);
}

// round 11
// speedup vs baseline: 1.1586x; 1.0025x over previous
#include <cuda_runtime.h>
#include <cuda_fp16.h>
#include <math.h>

#define MAX_N 50000
#define MAX_E 800000
#define CH    96
#define BN_EPS 1e-5f

// -------- scratch (device globals; no allocation allowed) --------
__device__ __half d_t [MAX_N * CH];      // GEMM output (fp16, gather input)
__device__ float  d_agg[MAX_N * CH];     // aggregation output (fp32)
__device__ float  d_stats[4 * CH];
__device__ int    d_deg   [MAX_N];
__device__ int    d_starts[MAX_N + 1];
__device__ int    d_cursor[MAX_N];
__device__ int2   d_epack [MAX_E];

// -------- packed f32x2 helpers --------
__device__ __forceinline__ unsigned long long ffma2(unsigned long long a,
                                                    unsigned long long b,
                                                    unsigned long long c) {
    unsigned long long d;
    asm("fma.rn.f32x2 %0, %1, %2, %3;" : "=l"(d) : "l"(a), "l"(b), "l"(c));
    return d;
}
__device__ __forceinline__ unsigned long long bcast2(float x) {
    unsigned long long d;
    asm("mov.b64 %0, {%1, %1};" : "=l"(d) : "f"(x));
    return d;
}
__device__ __forceinline__ float2 unpack2(unsigned long long p) {
    float lo, hi;
    asm("mov.b64 {%0, %1}, %2;" : "=f"(lo), "=f"(hi) : "l"(p));
    return make_float2(lo, hi);
}

// ============================================================================
// GEMM device body: TM=32 rows/block, 4x4 per thread, FFMA2 inner loop,
// K-chunked (KC=32). Optional fused BN+ReLU on input. fp16 output.
// ============================================================================
template<int CIN, int COUT>
__device__ __forceinline__ void gemm_bn_body(int bx,
                                             const float* __restrict__ A,
                                             const float* __restrict__ W,
                                             const float* __restrict__ stats,
                                             const float* __restrict__ gamma,
                                             const float* __restrict__ beta,
                                             __half* __restrict__ C, int nrows) {
    constexpr int TM = 32;
    constexpr int KC = 32;
    constexpr int TX = COUT / 4;
    constexpr int TY = TM / 4;
    constexpr int NT = TX * TY;
    constexpr int APAD = TM + 4;
    constexpr int KGC = KC / 4;

    __shared__ float Ws[KC * COUT];
    __shared__ float As[KC * APAD];
    __shared__ float Sc[CIN];
    __shared__ float Sh[CIN];

    int tid = threadIdx.y * TX + threadIdx.x;
    int row0 = bx * TM;
    int c0 = threadIdx.x * 4;
    int r0 = threadIdx.y * 4;

    bool has_bn = (gamma != nullptr);
    if (has_bn) {
        float n = (float)nrows;
        for (int i = tid; i < CIN; i += NT) {
            float mean = stats[i] / n;
            float var  = stats[CIN + i] / n - mean * mean;
            float inv  = rsqrtf(var + BN_EPS);
            float sc   = gamma[i] * inv;
            Sc[i] = sc;
            Sh[i] = beta[i] - mean * sc;
        }
        __syncthreads();
    }

    unsigned long long accp[2][4];
#pragma unroll
    for (int rp = 0; rp < 2; rp++)
#pragma unroll
        for (int c = 0; c < 4; c++) accp[rp][c] = 0ULL;

    for (int k0 = 0; k0 < CIN; k0 += KC) {
        for (int i = tid; i < KC * COUT / 4; i += NT)
            ((float4*)Ws)[i] = ((const float4*)(W + k0 * COUT))[i];
        for (int i = tid; i < TM * KGC; i += NT) {
            int r  = i / KGC;
            int kg = i % KGC;
            int grow = row0 + r;
            float4 v = make_float4(0.f, 0.f, 0.f, 0.f);
            if (grow < nrows)
                v = *(const float4*)(A + (long)grow * CIN + k0 + kg * 4);
            if (has_bn) {
                int k = k0 + kg * 4;
                v.x = fmaxf(fmaf(v.x, Sc[k+0], Sh[k+0]), 0.f);
                v.y = fmaxf(fmaf(v.y, Sc[k+1], Sh[k+1]), 0.f);
                v.z = fmaxf(fmaf(v.z, Sc[k+2], Sh[k+2]), 0.f);
                v.w = fmaxf(fmaf(v.w, Sc[k+3], Sh[k+3]), 0.f);
            }
            As[(kg*4+0) * APAD + r] = v.x;
            As[(kg*4+1) * APAD + r] = v.y;
            As[(kg*4+2) * APAD + r] = v.z;
            As[(kg*4+3) * APAD + r] = v.w;
        }
        __syncthreads();

#pragma unroll 8
        for (int kk = 0; kk < KC; kk++) {
            float4 w = *(const float4*)(Ws + kk * COUT + c0);
            ulonglong2 av = *(const ulonglong2*)(As + kk * APAD + r0);
            unsigned long long wx = bcast2(w.x), wy = bcast2(w.y);
            unsigned long long wz = bcast2(w.z), ww = bcast2(w.w);
            accp[0][0] = ffma2(av.x, wx, accp[0][0]);
            accp[0][1] = ffma2(av.x, wy, accp[0][1]);
            accp[0][2] = ffma2(av.x, wz, accp[0][2]);
            accp[0][3] = ffma2(av.x, ww, accp[0][3]);
            accp[1][0] = ffma2(av.y, wx, accp[1][0]);
            accp[1][1] = ffma2(av.y, wy, accp[1][1]);
            accp[1][2] = ffma2(av.y, wz, accp[1][2]);
            accp[1][3] = ffma2(av.y, ww, accp[1][3]);
        }
        __syncthreads();
    }

#pragma unroll
    for (int rp = 0; rp < 2; rp++) {
        float2 u0 = unpack2(accp[rp][0]);
        float2 u1 = unpack2(accp[rp][1]);
        float2 u2 = unpack2(accp[rp][2]);
        float2 u3 = unpack2(accp[rp][3]);
        int grow = row0 + r0 + rp * 2;
        if (grow < nrows) {
            __half2 h01 = __floats2half2_rn(u0.x, u1.x);
            __half2 h23 = __floats2half2_rn(u2.x, u3.x);
            uint2 pkt = make_uint2(*(unsigned*)&h01, *(unsigned*)&h23);
            *(uint2*)(C + (long)grow * COUT + c0) = pkt;
        }
        if (grow + 1 < nrows) {
            __half2 h01 = __floats2half2_rn(u0.y, u1.y);
            __half2 h23 = __floats2half2_rn(u2.y, u3.y);
            uint2 pkt = make_uint2(*(unsigned*)&h01, *(unsigned*)&h23);
            *(uint2*)(C + (long)(grow + 1) * COUT + c0) = pkt;
        }
    }
}

template<int CIN, int COUT>
__global__ void __launch_bounds__(192, 6)
gemm_bn_kernel(const float* __restrict__ A,
               const float* __restrict__ W,
               const float* __restrict__ stats,
               const float* __restrict__ gamma,
               const float* __restrict__ beta,
               __half* __restrict__ C, int nrows) {
    gemm_bn_body<CIN, COUT>(blockIdx.x, A, W, stats, gamma, beta, C, nrows);
}

// ---- fused: GEMM1 (blocks [0,gb)) + edge histogram (blocks [gb, gridDim)) ---
__global__ void __launch_bounds__(192, 6)
gemm1_hist_kernel(const float* __restrict__ A,
                  const float* __restrict__ W,
                  __half* __restrict__ C, int nrows, int gb,
                  const int* __restrict__ row, int* __restrict__ deg, int E) {
    if (blockIdx.x < gb) {
        gemm_bn_body<128, 96>(blockIdx.x, A, W, nullptr, nullptr, nullptr, C, nrows);
    } else {
        int nb = gridDim.x - gb;
        int i = (blockIdx.x - gb) * blockDim.x * blockDim.y
              + threadIdx.y * blockDim.x + threadIdx.x;
        int stride = nb * blockDim.x * blockDim.y;
        for (; i < E; i += stride) atomicAdd(&deg[row[i]], 1);
    }
}

// ============================================================================
// CSR build: scan (also zeros stats) -> permute
// ============================================================================
__global__ void scan_kernel(const int* __restrict__ deg,
                            int* __restrict__ starts,
                            int* __restrict__ cursor,
                            float* __restrict__ stats, int N) {
    __shared__ int part[1024];
    int t = threadIdx.x;
    if (t < 4 * CH) stats[t] = 0.f;
    int chunk = (N + 1023) / 1024;
    int lo = t * chunk;
    int hi = lo + chunk; if (hi > N) hi = N; if (lo > N) lo = N;
    int s = 0;
    for (int i = lo; i < hi; i++) s += deg[i];
    part[t] = s;
    __syncthreads();
    for (int o = 1; o < 1024; o <<= 1) {
        int v = (t >= o) ? part[t - o] : 0;
        __syncthreads();
        part[t] += v;
        __syncthreads();
    }
    int base = (t == 0) ? 0 : part[t - 1];
    for (int i = lo; i < hi; i++) {
        starts[i] = base;
        cursor[i] = base;
        base += deg[i];
    }
    if (t == 1023) starts[N] = part[1023];
}

__global__ void permute_kernel(const int* __restrict__ row,
                               const int* __restrict__ col,
                               const float* __restrict__ ew,
                               int* __restrict__ cursor,
                               int2* __restrict__ epack, int E) {
    int i = blockIdx.x * blockDim.x + threadIdx.x;
    if (i >= E) return;
    int p = atomicAdd(&cursor[row[i]], 1);
    epack[p] = make_int2(col[i], __float_as_int(ew[i]));
}

// ============================================================================
// CSR gather (96 ch, fp16 src): one warp per node, lanes 0-23 own 4-channel
// groups (uint2 = 4 halves = 8B). Unrolled by 8 edges (8 LDG.64 in flight).
// ============================================================================
__device__ __forceinline__ void h4fma(float4& acc, uint2 r, float w) {
    float2 f01 = __half22float2(*(__half2*)&r.x);
    float2 f23 = __half22float2(*(__half2*)&r.y);
    acc.x = fmaf(w, f01.x, acc.x);
    acc.y = fmaf(w, f01.y, acc.y);
    acc.z = fmaf(w, f23.x, acc.z);
    acc.w = fmaf(w, f23.y, acc.w);
}

__global__ void __launch_bounds__(256)
gather96_kernel(const int* __restrict__ starts,
                const int2* __restrict__ epack,
                const __half* __restrict__ src,
                float* __restrict__ dst, int N) {
    int w = (blockIdx.x * blockDim.x + threadIdx.x) >> 5;
    int lane = threadIdx.x & 31;
    if (w >= N) return;
    int s = __ldg(starts + w), e = __ldg(starts + w + 1);
    bool act = lane < 24;
    float4 acc0 = make_float4(0.f,0.f,0.f,0.f);
    float4 acc1 = make_float4(0.f,0.f,0.f,0.f);
    int i = s;
    // main loop: 8 edges, 8 independent row loads in flight
    for (; i + 7 < e; i += 8) {
        int2 p0 = __ldg(epack + i);
        int2 p1 = __ldg(epack + i + 1);
        int2 p2 = __ldg(epack + i + 2);
        int2 p3 = __ldg(epack + i + 3);
        int2 p4 = __ldg(epack + i + 4);
        int2 p5 = __ldg(epack + i + 5);
        int2 p6 = __ldg(epack + i + 6);
        int2 p7 = __ldg(epack + i + 7);
        uint2 v0 = make_uint2(0,0), v1 = v0, v2 = v0, v3 = v0;
        uint2 v4 = v0, v5 = v0, v6 = v0, v7 = v0;
        if (act) {
            v0 = __ldg(((const uint2*)(src + (long)p0.x * 96)) + lane);
            v1 = __ldg(((const uint2*)(src + (long)p1.x * 96)) + lane);
            v2 = __ldg(((const uint2*)(src + (long)p2.x * 96)) + lane);
            v3 = __ldg(((const uint2*)(src + (long)p3.x * 96)) + lane);
            v4 = __ldg(((const uint2*)(src + (long)p4.x * 96)) + lane);
            v5 = __ldg(((const uint2*)(src + (long)p5.x * 96)) + lane);
            v6 = __ldg(((const uint2*)(src + (long)p6.x * 96)) + lane);
            v7 = __ldg(((const uint2*)(src + (long)p7.x * 96)) + lane);
        }
        h4fma(acc0, v0, __int_as_float(p0.y));
        h4fma(acc1, v1, __int_as_float(p1.y));
        h4fma(acc0, v2, __int_as_float(p2.y));
        h4fma(acc1, v3, __int_as_float(p3.y));
        h4fma(acc0, v4, __int_as_float(p4.y));
        h4fma(acc1, v5, __int_as_float(p5.y));
        h4fma(acc0, v6, __int_as_float(p6.y));
        h4fma(acc1, v7, __int_as_float(p7.y));
    }
    for (; i + 3 < e; i += 4) {
        int2 p0 = __ldg(epack + i);
        int2 p1 = __ldg(epack + i + 1);
        int2 p2 = __ldg(epack + i + 2);
        int2 p3 = __ldg(epack + i + 3);
        uint2 v0 = make_uint2(0,0), v1 = v0, v2 = v0, v3 = v0;
        if (act) {
            v0 = __ldg(((const uint2*)(src + (long)p0.x * 96)) + lane);
            v1 = __ldg(((const uint2*)(src + (long)p1.x * 96)) + lane);
            v2 = __ldg(((const uint2*)(src + (long)p2.x * 96)) + lane);
            v3 = __ldg(((const uint2*)(src + (long)p3.x * 96)) + lane);
        }
        h4fma(acc0, v0, __int_as_float(p0.y));
        h4fma(acc1, v1, __int_as_float(p1.y));
        h4fma(acc0, v2, __int_as_float(p2.y));
        h4fma(acc1, v3, __int_as_float(p3.y));
    }
    for (; i < e; i++) {
        int2 p = __ldg(epack + i);
        uint2 v = make_uint2(0,0);
        if (act) v = __ldg(((const uint2*)(src + (long)p.x * 96)) + lane);
        h4fma(acc0, v, __int_as_float(p.y));
    }
    acc0.x += acc1.x; acc0.y += acc1.y; acc0.z += acc1.z; acc0.w += acc1.w;
    if (act) ((float4*)(dst + (long)w * 96))[lane] = acc0;
}

// ============================================================================
// CSR gather (64 ch, fp16 src): half-warps own alternating edges, unroll-4
// per half (8 edges in flight per warp). Fused +bias + log_softmax.
// ============================================================================
__global__ void __launch_bounds__(256)
gather64_lsm_kernel(const int* __restrict__ starts,
                    const int2* __restrict__ epack,
                    const __half* __restrict__ src,
                    const float* __restrict__ b,
                    float* __restrict__ out, int N) {
    int w = (blockIdx.x * blockDim.x + threadIdx.x) >> 5;
    int lane = threadIdx.x & 31;
    if (w >= N) return;
    int half_ = lane >> 4;
    int q = lane & 15;
    int s = __ldg(starts + w), e = __ldg(starts + w + 1);
    float4 acc0 = make_float4(0.f,0.f,0.f,0.f);
    float4 acc1 = make_float4(0.f,0.f,0.f,0.f);
    int i = s + half_;
    for (; i + 6 < e; i += 8) {
        int2 p0 = __ldg(epack + i);
        int2 p1 = __ldg(epack + i + 2);
        int2 p2 = __ldg(epack + i + 4);
        int2 p3 = __ldg(epack + i + 6);
        uint2 v0 = __ldg(((const uint2*)(src + (long)p0.x * 64)) + q);
        uint2 v1 = __ldg(((const uint2*)(src + (long)p1.x * 64)) + q);
        uint2 v2 = __ldg(((const uint2*)(src + (long)p2.x * 64)) + q);
        uint2 v3 = __ldg(((const uint2*)(src + (long)p3.x * 64)) + q);
        h4fma(acc0, v0, __int_as_float(p0.y));
        h4fma(acc1, v1, __int_as_float(p1.y));
        h4fma(acc0, v2, __int_as_float(p2.y));
        h4fma(acc1, v3, __int_as_float(p3.y));
    }
    for (; i + 2 < e; i += 4) {
        int2 p0 = __ldg(epack + i);
        int2 p1 = __ldg(epack + i + 2);
        uint2 v0 = __ldg(((const uint2*)(src + (long)p0.x * 64)) + q);
        uint2 v1 = __ldg(((const uint2*)(src + (long)p1.x * 64)) + q);
        h4fma(acc0, v0, __int_as_float(p0.y));
        h4fma(acc1, v1, __int_as_float(p1.y));
    }
    for (; i < e; i += 2) {
        int2 p = __ldg(epack + i);
        uint2 v = __ldg(((const uint2*)(src + (long)p.x * 64)) + q);
        h4fma(acc0, v, __int_as_float(p.y));
    }
    acc0.x += acc1.x; acc0.y += acc1.y; acc0.z += acc1.z; acc0.w += acc1.w;
    acc0.x += __shfl_xor_sync(0xFFFFFFFFu, acc0.x, 16);
    acc0.y += __shfl_xor_sync(0xFFFFFFFFu, acc0.y, 16);
    acc0.z += __shfl_xor_sync(0xFFFFFFFFu, acc0.z, 16);
    acc0.w += __shfl_xor_sync(0xFFFFFFFFu, acc0.w, 16);
    float4 bb = __ldg(((const float4*)b) + q);
    float v0 = acc0.x + bb.x, v1 = acc0.y + bb.y, v2 = acc0.z + bb.z, v3 = acc0.w + bb.w;
    float m = fmaxf(fmaxf(v0, v1), fmaxf(v2, v3));
#pragma unroll
    for (int o = 8; o; o >>= 1) m = fmaxf(m, __shfl_xor_sync(0xFFFFFFFFu, m, o));
    float sm = __expf(v0 - m) + __expf(v1 - m) + __expf(v2 - m) + __expf(v3 - m);
#pragma unroll
    for (int o = 8; o; o >>= 1) sm += __shfl_xor_sync(0xFFFFFFFFu, sm, o);
    float l = m + __logf(sm);
    if (half_ == 0)
        ((float4*)(out + (long)w * 64))[q] = make_float4(v0 - l, v1 - l, v2 - l, v3 - l);
}

// -------- BN stats: register-accumulating, one thread per channel ----------
__global__ void stats96_kernel(const float* __restrict__ h,
                               float* __restrict__ stats, int nrows) {
    int c = threadIdx.x;
    float s = 0.f, q = 0.f;
    for (int r = blockIdx.x; r < nrows; r += gridDim.x) {
        float v = h[(long)r * 96 + c];
        s += v;
        q = fmaf(v, v, q);
    }
    atomicAdd(&stats[c], s);
    atomicAdd(&stats[96 + c], q);
}

// ============================================================================
extern "C" void kernel_launch(void* const* d_in, const int* in_sizes, int n_in,
                              void* d_out, int out_size) {
    const float* x   = (const float*)d_in[0];
    const float* ew  = (const float*)d_in[1];
    const int*   row = (const int*)  d_in[2];
    const int*   col = (const int*)  d_in[3];
    const float* W1  = (const float*)d_in[4];
    // b1 = d_in[5]  -- absorbed exactly by BatchNorm mean, skipped
    const float* W2  = (const float*)d_in[6];
    // b2 = d_in[7]  -- absorbed exactly by BatchNorm mean, skipped
    const float* W3  = (const float*)d_in[8];
    const float* b3  = (const float*)d_in[9];
    const float* g1  = (const float*)d_in[10];
    const float* be1 = (const float*)d_in[11];
    const float* g2  = (const float*)d_in[12];
    const float* be2 = (const float*)d_in[13];

    int N = in_sizes[0] / 128;
    int E = in_sizes[1];
    if (N > MAX_N) N = MAX_N;
    if (E > MAX_E) E = MAX_E;
    float* out = (float*)d_out;

    __half* t;
    float *agg, *stats;
    int *deg, *starts, *cursor;
    int2 *epack;
    cudaGetSymbolAddress((void**)&t,      d_t);
    cudaGetSymbolAddress((void**)&agg,    d_agg);
    cudaGetSymbolAddress((void**)&stats,  d_stats);
    cudaGetSymbolAddress((void**)&deg,    d_deg);
    cudaGetSymbolAddress((void**)&starts, d_starts);
    cudaGetSymbolAddress((void**)&cursor, d_cursor);
    cudaGetSymbolAddress((void**)&epack,  d_epack);

    float* stats1 = stats;
    float* stats2 = stats + 2 * CH;

    int gblocks = (N + 31) / 32;
    int eblocks = (E + 255) / 256;
    int nwarp_blocks = (N * 32 + 255) / 256;
    int hblocks = 512;

    // ---------------- fused GEMM1 + histogram, then scan + permute ----------
    cudaMemsetAsync(deg, 0, (long)N * sizeof(int));
    gemm1_hist_kernel<<<gblocks + hblocks, dim3(24,8)>>>(x, W1, t, N, gblocks,
                                                         row, deg, E);
    scan_kernel<<<1, 1024>>>(deg, starts, cursor, stats, N);
    permute_kernel<<<eblocks, 256>>>(row, col, ew, cursor, epack, E);

    // ---------------- Layer 1 (aggregate + stats) ----------------
    gather96_kernel<<<nwarp_blocks, 256>>>(starts, epack, t, agg, N);
    stats96_kernel<<<1024, 96>>>(agg, stats1, N);

    // ---------------- Layer 2 ----------------
    gemm_bn_kernel<96,96><<<gblocks, dim3(24,8)>>>(agg, W2, stats1, g1, be1, t, N);
    gather96_kernel<<<nwarp_blocks, 256>>>(starts, epack, t, agg, N);
    stats96_kernel<<<1024, 96>>>(agg, stats2, N);

    // ---------------- Layer 3 ----------------
    gemm_bn_kernel<96,64><<<gblocks, dim3(16,8)>>>(agg, W3, stats2, g2, be2, t, N);
    gather64_lsm_kernel<<<nwarp_blocks, 256>>>(starts, epack, t, b3, out, N);
}

// round 13
// speedup vs baseline: 1.3605x; 1.1743x over previous
#include <cuda_runtime.h>
#include <cuda_fp16.h>
#include <cstdint>
#include <math.h>

#define MAX_N 50000
#define MAX_E 800000
#define CH    96
#define BN_EPS 1e-5f

// -------- scratch (device globals; no allocation allowed) --------
__device__ __half d_t [MAX_N * CH];      // GEMM output (fp16, gather input)
__device__ float  d_agg[MAX_N * CH];     // aggregation output (fp32)
__device__ float  d_stats[4 * CH];
__device__ int    d_deg   [MAX_N];
__device__ int    d_starts[MAX_N + 1];
__device__ int    d_cursor[MAX_N];
__device__ int2   d_epack [MAX_E];

// ============================================================================
// Tensor-core GEMM body (mma.sync m16n8k16, f16 in / f32 accum / f16 out).
// Block: 256 threads = 8 warps as 4(M) x 2(N); tile 64 x COUT.
// A (fp32, optionally BN+ReLU'd) and W (fp32) staged to fp16 smem.
// ============================================================================
template<int CIN, int COUT>
__device__ __forceinline__ void gemm_mma_body(int bx,
                                              const float* __restrict__ A,
                                              const float* __restrict__ W,
                                              const float* __restrict__ stats,
                                              const float* __restrict__ gamma,
                                              const float* __restrict__ beta,
                                              __half* __restrict__ C, int nrows) {
    constexpr int TM = 64;
    constexpr int SA = CIN + 8;    // As stride (halves); *2B is 16B-multiple
    constexpr int SW = COUT + 8;   // Ws stride (halves)
    constexpr int WN = COUT / 2;   // warp N extent (48 or 32)
    constexpr int NT = WN / 8;     // n-tiles per warp (6 or 4)

    __shared__ __half As[TM * SA];
    __shared__ __half Ws[CIN * SW];
    __shared__ float  Sc[CIN];
    __shared__ float  Sh[CIN];

    int tid = threadIdx.x;
    int row0 = bx * TM;
    bool has_bn = (gamma != nullptr);

    if (has_bn) {
        float n = (float)nrows;
        for (int i = tid; i < CIN; i += 256) {
            float mean = stats[i] / n;
            float var  = stats[CIN + i] / n - mean * mean;
            float inv  = rsqrtf(var + BN_EPS);
            float sc   = gamma[i] * inv;
            Sc[i] = sc;
            Sh[i] = beta[i] - mean * sc;
        }
        __syncthreads();
    }

    // stage W -> fp16 smem
    for (int i = tid; i < CIN * COUT / 4; i += 256) {
        int k  = i / (COUT / 4);
        int c4 = (i % (COUT / 4)) * 4;
        float4 wv = *(const float4*)(W + (long)k * COUT + c4);
        *(__half2*)(Ws + k * SW + c4)     = __floats2half2_rn(wv.x, wv.y);
        *(__half2*)(Ws + k * SW + c4 + 2) = __floats2half2_rn(wv.z, wv.w);
    }
    // stage A -> fp16 smem (BN+ReLU fused)
    for (int i = tid; i < TM * CIN / 4; i += 256) {
        int r  = i / (CIN / 4);
        int k4 = (i % (CIN / 4)) * 4;
        int grow = row0 + r;
        float4 v = make_float4(0.f, 0.f, 0.f, 0.f);
        if (grow < nrows)
            v = *(const float4*)(A + (long)grow * CIN + k4);
        if (has_bn) {
            v.x = fmaxf(fmaf(v.x, Sc[k4+0], Sh[k4+0]), 0.f);
            v.y = fmaxf(fmaf(v.y, Sc[k4+1], Sh[k4+1]), 0.f);
            v.z = fmaxf(fmaf(v.z, Sc[k4+2], Sh[k4+2]), 0.f);
            v.w = fmaxf(fmaf(v.w, Sc[k4+3], Sh[k4+3]), 0.f);
        }
        *(__half2*)(As + r * SA + k4)     = __floats2half2_rn(v.x, v.y);
        *(__half2*)(As + r * SA + k4 + 2) = __floats2half2_rn(v.z, v.w);
    }
    __syncthreads();

    int wid  = tid >> 5;
    int lane = tid & 31;
    int mrow = (wid & 3) * 16;        // warp M offset in tile
    int ncb  = (wid >> 2) * WN;       // warp N base

    float d[NT][4];
#pragma unroll
    for (int nt = 0; nt < NT; nt++) {
        d[nt][0] = 0.f; d[nt][1] = 0.f; d[nt][2] = 0.f; d[nt][3] = 0.f;
    }

    uint32_t as_base = (uint32_t)__cvta_generic_to_shared(As);
    uint32_t ws_base = (uint32_t)__cvta_generic_to_shared(Ws);
    int l15 = lane & 15;

#pragma unroll
    for (int k0 = 0; k0 < CIN; k0 += 16) {
        // A fragment: 16x16, row-major
        uint32_t a0, a1, a2, a3;
        uint32_t a_addr = as_base +
            (uint32_t)(((mrow + l15) * SA + k0 + ((lane >> 4) << 3)) * 2);
        asm volatile(
            "ldmatrix.sync.aligned.m8n8.x4.shared.b16 {%0,%1,%2,%3}, [%4];"
            : "=r"(a0), "=r"(a1), "=r"(a2), "=r"(a3) : "r"(a_addr));

#pragma unroll
        for (int nt = 0; nt < NT; nt++) {
            // B fragment: 16(k) x 8(n) from row-major Ws, transposed load
            uint32_t b0, b1;
            uint32_t b_addr = ws_base +
                (uint32_t)(((k0 + l15) * SW + ncb + nt * 8) * 2);
            asm volatile(
                "ldmatrix.sync.aligned.m8n8.x2.trans.shared.b16 {%0,%1}, [%2];"
                : "=r"(b0), "=r"(b1) : "r"(b_addr));
            asm volatile(
                "mma.sync.aligned.m16n8k16.row.col.f32.f16.f16.f32 "
                "{%0,%1,%2,%3}, {%4,%5,%6,%7}, {%8,%9}, {%0,%1,%2,%3};"
                : "+f"(d[nt][0]), "+f"(d[nt][1]), "+f"(d[nt][2]), "+f"(d[nt][3])
                : "r"(a0), "r"(a1), "r"(a2), "r"(a3), "r"(b0), "r"(b1));
        }
    }

    // epilogue: fp16 stores (half2 per d-pair)
    int erow = row0 + mrow + (lane >> 2);
#pragma unroll
    for (int nt = 0; nt < NT; nt++) {
        int col = ncb + nt * 8 + (lane & 3) * 2;
        if (erow < nrows)
            *(__half2*)(C + (long)erow * COUT + col) = __floats2half2_rn(d[nt][0], d[nt][1]);
        if (erow + 8 < nrows)
            *(__half2*)(C + (long)(erow + 8) * COUT + col) = __floats2half2_rn(d[nt][2], d[nt][3]);
    }
}

template<int CIN, int COUT>
__global__ void __launch_bounds__(256)
gemm_bn_kernel(const float* __restrict__ A,
               const float* __restrict__ W,
               const float* __restrict__ stats,
               const float* __restrict__ gamma,
               const float* __restrict__ beta,
               __half* __restrict__ C, int nrows) {
    gemm_mma_body<CIN, COUT>(blockIdx.x, A, W, stats, gamma, beta, C, nrows);
}

// ---- fused: GEMM1 (blocks [0,gb)) + edge histogram (blocks [gb, gridDim)) ---
__global__ void __launch_bounds__(256)
gemm1_hist_kernel(const float* __restrict__ A,
                  const float* __restrict__ W,
                  __half* __restrict__ C, int nrows, int gb,
                  const int* __restrict__ row, int* __restrict__ deg, int E) {
    if (blockIdx.x < gb) {
        gemm_mma_body<128, 96>(blockIdx.x, A, W, nullptr, nullptr, nullptr, C, nrows);
    } else {
        int nb = gridDim.x - gb;
        int i = (blockIdx.x - gb) * 256 + threadIdx.x;
        int stride = nb * 256;
        for (; i < E; i += stride) atomicAdd(&deg[row[i]], 1);
    }
}

// ============================================================================
// CSR build: scan (also zeros stats) -> permute
// ============================================================================
__global__ void scan_kernel(const int* __restrict__ deg,
                            int* __restrict__ starts,
                            int* __restrict__ cursor,
                            float* __restrict__ stats, int N) {
    __shared__ int part[1024];
    int t = threadIdx.x;
    if (t < 4 * CH) stats[t] = 0.f;
    int chunk = (N + 1023) / 1024;
    int lo = t * chunk;
    int hi = lo + chunk; if (hi > N) hi = N; if (lo > N) lo = N;
    int s = 0;
    for (int i = lo; i < hi; i++) s += deg[i];
    part[t] = s;
    __syncthreads();
    for (int o = 1; o < 1024; o <<= 1) {
        int v = (t >= o) ? part[t - o] : 0;
        __syncthreads();
        part[t] += v;
        __syncthreads();
    }
    int base = (t == 0) ? 0 : part[t - 1];
    for (int i = lo; i < hi; i++) {
        starts[i] = base;
        cursor[i] = base;
        base += deg[i];
    }
    if (t == 1023) starts[N] = part[1023];
}

__global__ void permute_kernel(const int* __restrict__ row,
                               const int* __restrict__ col,
                               const float* __restrict__ ew,
                               int* __restrict__ cursor,
                               int2* __restrict__ epack, int E) {
    int i = blockIdx.x * blockDim.x + threadIdx.x;
    if (i >= E) return;
    int p = atomicAdd(&cursor[row[i]], 1);
    epack[p] = make_int2(col[i], __float_as_int(ew[i]));
}

// ============================================================================
// CSR gather (96 ch, fp16 src): one warp per node, lanes 0-23 own 4-channel
// groups (uint2 = 4 halves = 8B). Unrolled by 4 edges. fp32 accumulate.
// ============================================================================
__device__ __forceinline__ void h4fma(float4& acc, uint2 r, float w) {
    float2 f01 = __half22float2(*(__half2*)&r.x);
    float2 f23 = __half22float2(*(__half2*)&r.y);
    acc.x = fmaf(w, f01.x, acc.x);
    acc.y = fmaf(w, f01.y, acc.y);
    acc.z = fmaf(w, f23.x, acc.z);
    acc.w = fmaf(w, f23.y, acc.w);
}

__global__ void gather96_kernel(const int* __restrict__ starts,
                                const int2* __restrict__ epack,
                                const __half* __restrict__ src,
                                float* __restrict__ dst, int N) {
    int w = (blockIdx.x * blockDim.x + threadIdx.x) >> 5;
    int lane = threadIdx.x & 31;
    if (w >= N) return;
    int s = __ldg(starts + w), e = __ldg(starts + w + 1);
    bool act = lane < 24;
    float4 acc0 = make_float4(0.f,0.f,0.f,0.f);
    float4 acc1 = make_float4(0.f,0.f,0.f,0.f);
    int i = s;
    for (; i + 3 < e; i += 4) {
        int2 p0 = __ldg(epack + i);
        int2 p1 = __ldg(epack + i + 1);
        int2 p2 = __ldg(epack + i + 2);
        int2 p3 = __ldg(epack + i + 3);
        uint2 v0 = make_uint2(0,0), v1 = v0, v2 = v0, v3 = v0;
        if (act) {
            v0 = __ldg(((const uint2*)(src + (long)p0.x * 96)) + lane);
            v1 = __ldg(((const uint2*)(src + (long)p1.x * 96)) + lane);
            v2 = __ldg(((const uint2*)(src + (long)p2.x * 96)) + lane);
            v3 = __ldg(((const uint2*)(src + (long)p3.x * 96)) + lane);
        }
        h4fma(acc0, v0, __int_as_float(p0.y));
        h4fma(acc1, v1, __int_as_float(p1.y));
        h4fma(acc0, v2, __int_as_float(p2.y));
        h4fma(acc1, v3, __int_as_float(p3.y));
    }
    for (; i < e; i++) {
        int2 p = __ldg(epack + i);
        uint2 v = make_uint2(0,0);
        if (act) v = __ldg(((const uint2*)(src + (long)p.x * 96)) + lane);
        h4fma(acc0, v, __int_as_float(p.y));
    }
    acc0.x += acc1.x; acc0.y += acc1.y; acc0.z += acc1.z; acc0.w += acc1.w;
    if (act) ((float4*)(dst + (long)w * 96))[lane] = acc0;
}

// ============================================================================
// CSR gather (64 ch, fp16 src): half-warps own alternating edges, unroll-2
// per half. Fused +bias + log_softmax.
// ============================================================================
__global__ void gather64_lsm_kernel(const int* __restrict__ starts,
                                    const int2* __restrict__ epack,
                                    const __half* __restrict__ src,
                                    const float* __restrict__ b,
                                    float* __restrict__ out, int N) {
    int w = (blockIdx.x * blockDim.x + threadIdx.x) >> 5;
    int lane = threadIdx.x & 31;
    if (w >= N) return;
    int half_ = lane >> 4;
    int q = lane & 15;
    int s = __ldg(starts + w), e = __ldg(starts + w + 1);
    float4 acc0 = make_float4(0.f,0.f,0.f,0.f);
    float4 acc1 = make_float4(0.f,0.f,0.f,0.f);
    int i = s + half_;
    for (; i + 2 < e; i += 4) {
        int2 p0 = __ldg(epack + i);
        int2 p1 = __ldg(epack + i + 2);
        uint2 v0 = __ldg(((const uint2*)(src + (long)p0.x * 64)) + q);
        uint2 v1 = __ldg(((const uint2*)(src + (long)p1.x * 64)) + q);
        h4fma(acc0, v0, __int_as_float(p0.y));
        h4fma(acc1, v1, __int_as_float(p1.y));
    }
    for (; i < e; i += 2) {
        int2 p = __ldg(epack + i);
        uint2 v = __ldg(((const uint2*)(src + (long)p.x * 64)) + q);
        h4fma(acc0, v, __int_as_float(p.y));
    }
    acc0.x += acc1.x; acc0.y += acc1.y; acc0.z += acc1.z; acc0.w += acc1.w;
    acc0.x += __shfl_xor_sync(0xFFFFFFFFu, acc0.x, 16);
    acc0.y += __shfl_xor_sync(0xFFFFFFFFu, acc0.y, 16);
    acc0.z += __shfl_xor_sync(0xFFFFFFFFu, acc0.z, 16);
    acc0.w += __shfl_xor_sync(0xFFFFFFFFu, acc0.w, 16);
    float4 bb = __ldg(((const float4*)b) + q);
    float v0 = acc0.x + bb.x, v1 = acc0.y + bb.y, v2 = acc0.z + bb.z, v3 = acc0.w + bb.w;
    float m = fmaxf(fmaxf(v0, v1), fmaxf(v2, v3));
#pragma unroll
    for (int o = 8; o; o >>= 1) m = fmaxf(m, __shfl_xor_sync(0xFFFFFFFFu, m, o));
    float sm = __expf(v0 - m) + __expf(v1 - m) + __expf(v2 - m) + __expf(v3 - m);
#pragma unroll
    for (int o = 8; o; o >>= 1) sm += __shfl_xor_sync(0xFFFFFFFFu, sm, o);
    float l = m + __logf(sm);
    if (half_ == 0)
        ((float4*)(out + (long)w * 64))[q] = make_float4(v0 - l, v1 - l, v2 - l, v3 - l);
}

// -------- BN stats: register-accumulating, one thread per channel ----------
__global__ void stats96_kernel(const float* __restrict__ h,
                               float* __restrict__ stats, int nrows) {
    int c = threadIdx.x;
    float s = 0.f, q = 0.f;
    for (int r = blockIdx.x; r < nrows; r += gridDim.x) {
        float v = h[(long)r * 96 + c];
        s += v;
        q = fmaf(v, v, q);
    }
    atomicAdd(&stats[c], s);
    atomicAdd(&stats[96 + c], q);
}

// ============================================================================
extern "C" void kernel_launch(void* const* d_in, const int* in_sizes, int n_in,
                              void* d_out, int out_size) {
    const float* x   = (const float*)d_in[0];
    const float* ew  = (const float*)d_in[1];
    const int*   row = (const int*)  d_in[2];
    const int*   col = (const int*)  d_in[3];
    const float* W1  = (const float*)d_in[4];
    // b1 = d_in[5]  -- absorbed exactly by BatchNorm mean, skipped
    const float* W2  = (const float*)d_in[6];
    // b2 = d_in[7]  -- absorbed exactly by BatchNorm mean, skipped
    const float* W3  = (const float*)d_in[8];
    const float* b3  = (const float*)d_in[9];
    const float* g1  = (const float*)d_in[10];
    const float* be1 = (const float*)d_in[11];
    const float* g2  = (const float*)d_in[12];
    const float* be2 = (const float*)d_in[13];

    int N = in_sizes[0] / 128;
    int E = in_sizes[1];
    if (N > MAX_N) N = MAX_N;
    if (E > MAX_E) E = MAX_E;
    float* out = (float*)d_out;

    __half* t;
    float *agg, *stats;
    int *deg, *starts, *cursor;
    int2 *epack;
    cudaGetSymbolAddress((void**)&t,      d_t);
    cudaGetSymbolAddress((void**)&agg,    d_agg);
    cudaGetSymbolAddress((void**)&stats,  d_stats);
    cudaGetSymbolAddress((void**)&deg,    d_deg);
    cudaGetSymbolAddress((void**)&starts, d_starts);
    cudaGetSymbolAddress((void**)&cursor, d_cursor);
    cudaGetSymbolAddress((void**)&epack,  d_epack);

    float* stats1 = stats;
    float* stats2 = stats + 2 * CH;

    int gblocks = (N + 63) / 64;
    int eblocks = (E + 255) / 256;
    int nwarp_blocks = (N * 32 + 255) / 256;
    int hblocks = 512;

    // ---------------- fused GEMM1 + histogram, then scan + permute ----------
    cudaMemsetAsync(deg, 0, (long)N * sizeof(int));
    gemm1_hist_kernel<<<gblocks + hblocks, 256>>>(x, W1, t, N, gblocks,
                                                  row, deg, E);
    scan_kernel<<<1, 1024>>>(deg, starts, cursor, stats, N);
    permute_kernel<<<eblocks, 256>>>(row, col, ew, cursor, epack, E);

    // ---------------- Layer 1 (aggregate + stats) ----------------
    gather96_kernel<<<nwarp_blocks, 256>>>(starts, epack, t, agg, N);
    stats96_kernel<<<1024, 96>>>(agg, stats1, N);

    // ---------------- Layer 2 ----------------
    gemm_bn_kernel<96,96><<<gblocks, 256>>>(agg, W2, stats1, g1, be1, t, N);
    gather96_kernel<<<nwarp_blocks, 256>>>(starts, epack, t, agg, N);
    stats96_kernel<<<1024, 96>>>(agg, stats2, N);

    // ---------------- Layer 3 ----------------
    gemm_bn_kernel<96,64><<<gblocks, 256>>>(agg, W3, stats2, g2, be2, t, N);
    gather64_lsm_kernel<<<nwarp_blocks, 256>>>(starts, epack, t, b3, out, N);
}